// round 8
// baseline (speedup 1.0000x reference)
#include <cuda_runtime.h>
#include <cuda_bf16.h>
#include <cstddef>

// CTC forward loss, probability-domain DP, warp-per-row, barrier-free.
// B=256, T=512, C=1024, L=64, S=129.
// R8: gather loads switched from __ldg (LDG.E.CONSTANT, 128B-promoting fill
// path) to ld.global.cg (L2-only coherent path, sector-granularity fill) to
// cut DRAM over-fetch on the random 4B gather. Everything else unchanged:
// one-warp CTAs (256 CTAs across all SMs), 16-deep prefetch ring, 6 states
// per lane, one shfl_up per step, power-of-2 renorm to 2^80 every 4 steps.

#define FULLMASK 0xffffffffu
#define EPSV 1e-7f

namespace {
constexpr int Tt = 512;
constexpr int Cc = 1024;
constexpr int Ll = 64;
constexpr int BLANK = Cc - 1;
constexpr int Dp = 16;           // prefetch ring depth (steps)
}

__device__ __forceinline__ float ldcg(const float* p) {
    float v;
    asm("ld.global.cg.f32 %0, [%1];" : "=f"(v) : "l"(p));
    return v;
}

__device__ __forceinline__ float pick6(float a0, float a1, float a2,
                                       float a3, float a4, float a5, int j) {
    float r = a0;
    r = (j == 1) ? a1 : r;
    r = (j == 2) ? a2 : r;
    r = (j == 3) ? a3 : r;
    r = (j == 4) ? a4 : r;
    r = (j == 5) ? a5 : r;
    return r;
}

__global__ __launch_bounds__(32, 1)
void ctc_warp_kernel(const int* __restrict__ y_true,
                     const float* __restrict__ y_pred,
                     float* __restrict__ out, int B)
{
    const int lane = threadIdx.x & 31;
    const int b = blockIdx.x;
    if (b >= B) return;

    const int*   yt  = y_true + b * Ll;
    const float* lpb = y_pred + (size_t)b * Tt * Cc;

    // ---- label length via ballots (Ll = 64 = 2 x 32) ----
    const int va = yt[lane];
    const int vb = yt[lane + 32];
    const int ll = __popc(__ballot_sync(FULLMASK, va != -1)) +
                   __popc(__ballot_sync(FULLMASK, vb != -1));
    const int Svalid = 2 * ll + 1;

    // ---- labels this lane needs: indices 3*lane-1 .. 3*lane+2 ----
    auto labAt = [&](int idx) -> int {
        if (idx < 0 || idx >= Ll) return BLANK;
        const int v = yt[idx];
        return (v < 0) ? BLANK : v;
    };
    const int base3 = 3 * lane;
    const int cm1 = labAt(base3 - 1);
    const int c0  = labAt(base3);       // class of state 6l+1
    const int c1  = labAt(base3 + 1);   // class of state 6l+3
    const int c2  = labAt(base3 + 2);   // class of state 6l+5

    // ---- per-state constants ----
    const int s0 = 6 * lane;
    const bool v0 = (s0 + 0) < Svalid;
    const bool v1 = (s0 + 1) < Svalid;
    const bool v2 = (s0 + 2) < Svalid;
    const bool v3 = (s0 + 3) < Svalid;
    const bool v4 = (s0 + 4) < Svalid;
    const bool v5 = (s0 + 5) < Svalid;
    // allow2 only on odd (label) states: ext[s]!=blank && ext[s]!=ext[s-2]
    const float M1 = ((s0 + 1) >= 2 && c0 != BLANK && c0 != cm1) ? 1.f : 0.f;
    const float M3 = ((s0 + 3) >= 2 && c1 != BLANK && c1 != c0)  ? 1.f : 0.f;
    const float M5 = ((s0 + 5) >= 2 && c2 != BLANK && c2 != c1)  ? 1.f : 0.f;

    // ---- alpha registers, t = 0 init (biased by 2^40 for early headroom) ----
    const float BIAS = __uint_as_float((unsigned)(40 + 127) << 23);  // 2^40
    float a0 = 0.f, a1 = 0.f, a2 = 0.f, a3 = 0.f, a4 = 0.f, a5 = 0.f;
    if (lane == 0) {
        a0 = (ldcg(lpb + BLANK) + EPSV) * BIAS;             // s=0 always valid
        if (ll > 0) a1 = (ldcg(lpb + c0) + EPSV) * BIAS;    // s=1 iff ll>=1
    }
    int kAcc = -40;  // accumulated power-of-2 exponent removed by renorms

    // ---- prefetch ring: slot i holds p[t] for step t with (t-1)&15 == i ----
    float pb[Dp], p0[Dp], p1[Dp], p2[Dp];
    #pragma unroll
    for (int i = 0; i < Dp; ++i) {
        const float* pt = lpb + (size_t)(1 + i) * Cc;
        pb[i] = ldcg(pt + BLANK);
        p0[i] = ldcg(pt + c0);
        p1[i] = ldcg(pt + c1);
        p2[i] = ldcg(pt + c2);
    }

    // exact power-of-2 renorm: bring warp-max exponent to +80
    auto renorm = [&]() {
        float m = fmaxf(fmaxf(fmaxf(a0, a1), fmaxf(a2, a3)), fmaxf(a4, a5));
        const unsigned mi = __reduce_max_sync(FULLMASK, __float_as_uint(m));
        const unsigned ebits = mi & 0x7f800000u;
        if (ebits != 0u) {                                   // uniform branch
            const int Ei = (int)(ebits >> 23);               // biased exponent
            // scale = 2^(80 - (Ei-127)) = 2^(207-Ei); field = 334-Ei
            const float rs = __uint_as_float((unsigned)(334 - Ei) << 23);
            a0 *= rs; a1 *= rs; a2 *= rs; a3 *= rs; a4 *= rs; a5 *= rs;
            kAcc += Ei - 207;                                // Ei-127-80
        }
    };

    // ---- main scan: t = 1 .. T-1, unrolled by 16, renorm every 4 steps ----
    for (int t0 = 1; t0 < Tt; t0 += Dp) {
        #pragma unroll
        for (int j = 0; j < Dp; ++j) {
            const int t = t0 + j;
            if (t < Tt) {
                // emissions for step t (slot j), validity folded in
                const float ebv = pb[j] + EPSV;
                const float E0 = v0 ? ebv : 0.f;
                const float E1 = v1 ? (p0[j] + EPSV) : 0.f;
                const float E2 = v2 ? ebv : 0.f;
                const float E3 = v3 ? (p1[j] + EPSV) : 0.f;
                const float E4 = v4 ? ebv : 0.f;
                const float E5 = v5 ? (p2[j] + EPSV) : 0.f;

                // refill this slot with p[t + Dp]
                int tl = t + Dp; if (tl > Tt - 1) tl = Tt - 1;
                const float* pt = lpb + (size_t)tl * Cc;
                pb[j] = ldcg(pt + BLANK);
                p0[j] = ldcg(pt + c0);
                p1[j] = ldcg(pt + c1);
                p2[j] = ldcg(pt + c2);

                // cross-lane neighbor: lane l-1's a5 (= s0-1; also skip src of s0+1)
                float n1 = __shfl_up_sync(FULLMASK, a5, 1);
                n1 = (lane == 0) ? 0.f : n1;

                const float t0v = E0 * (a0 + n1);                 // blank: no skip
                const float t1v = E1 * fmaf(M1, n1, a1 + a0);
                const float t2v = E2 * (a2 + a1);
                const float t3v = E3 * fmaf(M3, a1, a3 + a2);
                const float t4v = E4 * (a4 + a3);
                const float t5v = E5 * fmaf(M5, a3, a5 + a4);
                a0 = t0v; a1 = t1v; a2 = t2v; a3 = t3v; a4 = t4v; a5 = t5v;
            }
            if ((j & 3) == 3) renorm();    // 4-step renorm cadence
        }
    }

    // ---- epilogue: loss = -( log(a[2ll] + a[2ll-1]) + kAcc*ln2 ) ----
    const int sl = 2 * ll;
    float vl = pick6(a0, a1, a2, a3, a4, a5, sl % 6);
    vl = __shfl_sync(FULLMASK, vl, sl / 6);
    float vp = 0.f;
    if (ll > 0) {                                            // uniform
        const int sp = sl - 1;
        float t = pick6(a0, a1, a2, a3, a4, a5, sp % 6);
        vp = __shfl_sync(FULLMASK, t, sp / 6);
    }
    if (lane == 0) {
        out[b] = -(__logf(vl + vp) + (float)kAcc * 0.6931471805599453f);
    }
}

extern "C" void kernel_launch(void* const* d_in, const int* in_sizes, int n_in,
                              void* d_out, int out_size)
{
    const void* q0 = d_in[0];
    const void* q1 = d_in[1];
    const int*   y_true;
    const float* y_pred;
    if (in_sizes[0] < in_sizes[1]) {
        y_true = (const int*)q0;
        y_pred = (const float*)q1;
    } else {
        y_true = (const int*)q1;
        y_pred = (const float*)q0;
    }
    float* out = (float*)d_out;

    const int B = out_size;                 // one loss per row
    ctc_warp_kernel<<<B, 32>>>(y_true, y_pred, out, B);  // 1 warp per CTA
}

// round 10
// speedup vs baseline: 1.0357x; 1.0357x over previous
#include <cuda_runtime.h>
#include <cuda_bf16.h>
#include <cstddef>

// CTC forward loss, probability-domain DP, warp-per-row, barrier-free.
// B=256, T=512, C=1024, L=64, S=129.
// R9: sorted gather. Labels are time-invariant, so we rank-sort them once
// and each step issues 2 address-sorted LDGs (14 L1tex wavefronts each vs
// ~26 for random order) + 1 uniform blank load (1 wavefront), instead of 4
// random-gather LDGs (~104 wavefronts). Values are routed to DP lanes with
// 6 shuffles/step via a precomputed rank table. __ldg restored (R8 showed
// ld.global.cg regresses; DRAM bytes are 128B-line invariant either way).

#define FULLMASK 0xffffffffu
#define EPSV 1e-7f

namespace {
constexpr int Tt = 512;
constexpr int Cc = 1024;
constexpr int Ll = 64;
constexpr int BLANK = Cc - 1;
constexpr int Dp = 16;           // prefetch ring depth (steps)
}

__device__ __forceinline__ float pick6(float a0, float a1, float a2,
                                       float a3, float a4, float a5, int j) {
    float r = a0;
    r = (j == 1) ? a1 : r;
    r = (j == 2) ? a2 : r;
    r = (j == 3) ? a3 : r;
    r = (j == 4) ? a4 : r;
    r = (j == 5) ? a5 : r;
    return r;
}

__global__ __launch_bounds__(32, 1)
void ctc_warp_kernel(const int* __restrict__ y_true,
                     const float* __restrict__ y_pred,
                     float* __restrict__ out, int B)
{
    const int lane = threadIdx.x & 31;
    const int b = blockIdx.x;
    if (b >= B) return;

    const int*   yt  = y_true + b * Ll;
    const float* lpb = y_pred + (size_t)b * Tt * Cc;

    __shared__ int s_cls[Ll];    // class value at sorted slot
    __shared__ int s_rank[Ll];   // sorted slot of original label index

    // ---- load labels (mapped: -1 -> BLANK), label length via ballots ----
    const int rawA = yt[lane];
    const int rawB = yt[lane + 32];
    const int A  = (rawA < 0) ? BLANK : rawA;   // label index lane
    const int Bv = (rawB < 0) ? BLANK : rawB;   // label index lane+32
    const int ll = __popc(__ballot_sync(FULLMASK, rawA != -1)) +
                   __popc(__ballot_sync(FULLMASK, rawB != -1));
    const int Svalid = 2 * ll + 1;

    // ---- rank-sort the 64 labels (stable: tie-break by index) ----
    int rA = 0, rB = 0;
    #pragma unroll
    for (int k = 0; k < 32; ++k) {
        const int xa = __shfl_sync(FULLMASK, A,  k);
        const int xb = __shfl_sync(FULLMASK, Bv, k);
        rA += (xa < A)  || (xa == A  && k        < lane);
        rA += (xb < A)  || (xb == A  && (k + 32) < lane);
        rB += (xa < Bv) || (xa == Bv && k        < (lane + 32));
        rB += (xb < Bv) || (xb == Bv && (k + 32) < (lane + 32));
    }
    s_rank[lane]      = rA;
    s_rank[lane + 32] = rB;
    s_cls[rA] = A;
    s_cls[rB] = Bv;
    __syncwarp();

    // sorted-slot classes this lane loads each step
    const int cls0 = s_cls[lane];        // slot lane      (0..31)
    const int cls1 = s_cls[lane + 32];   // slot lane+32   (32..63)

    // ---- labels / routes this lane's states need ----
    auto labAt = [&](int idx) -> int {
        if (idx < 0 || idx >= Ll) return BLANK;
        const int v = yt[idx];
        return (v < 0) ? BLANK : v;
    };
    const int base3 = 3 * lane;
    const int cm1 = labAt(base3 - 1);
    const int c0  = labAt(base3);        // class of state 6l+1
    const int c1  = labAt(base3 + 1);    // class of state 6l+3
    const int c2  = labAt(base3 + 2);    // class of state 6l+5
    // sorted slot of each needed label; 64 = sentinel "use blank register"
    const int r0 = (base3     < Ll) ? s_rank[base3]     : Ll;
    const int r1 = (base3 + 1 < Ll) ? s_rank[base3 + 1] : Ll;
    const int r2 = (base3 + 2 < Ll) ? s_rank[base3 + 2] : Ll;

    // ---- per-state constants ----
    const int s0 = 6 * lane;
    const bool v0 = (s0 + 0) < Svalid;
    const bool v1 = (s0 + 1) < Svalid;
    const bool v2 = (s0 + 2) < Svalid;
    const bool v3 = (s0 + 3) < Svalid;
    const bool v4 = (s0 + 4) < Svalid;
    const bool v5 = (s0 + 5) < Svalid;
    const float M1 = ((s0 + 1) >= 2 && c0 != BLANK && c0 != cm1) ? 1.f : 0.f;
    const float M3 = ((s0 + 3) >= 2 && c1 != BLANK && c1 != c0)  ? 1.f : 0.f;
    const float M5 = ((s0 + 5) >= 2 && c2 != BLANK && c2 != c1)  ? 1.f : 0.f;

    // ---- alpha registers, t = 0 init (biased by 2^40) ----
    const float BIAS = __uint_as_float((unsigned)(40 + 127) << 23);  // 2^40
    float a0 = 0.f, a1 = 0.f, a2 = 0.f, a3 = 0.f, a4 = 0.f, a5 = 0.f;
    if (lane == 0) {
        a0 = (__ldg(lpb + BLANK) + EPSV) * BIAS;
        if (ll > 0) a1 = (__ldg(lpb + c0) + EPSV) * BIAS;
    }
    int kAcc = -40;

    // ---- prefetch ring (sorted-slot values + blank) ----
    float q0[Dp], q1[Dp], qb[Dp];
    #pragma unroll
    for (int i = 0; i < Dp; ++i) {
        const float* pt = lpb + (size_t)(1 + i) * Cc;
        q0[i] = __ldg(pt + cls0);
        q1[i] = __ldg(pt + cls1);
        qb[i] = __ldg(pt + BLANK);      // uniform address: 1 wavefront
    }

    // exact power-of-2 renorm: bring warp-max exponent to +80
    auto renorm = [&]() {
        float m = fmaxf(fmaxf(fmaxf(a0, a1), fmaxf(a2, a3)), fmaxf(a4, a5));
        const unsigned mi = __reduce_max_sync(FULLMASK, __float_as_uint(m));
        const unsigned ebits = mi & 0x7f800000u;
        if (ebits != 0u) {
            const int Ei = (int)(ebits >> 23);
            const float rs = __uint_as_float((unsigned)(334 - Ei) << 23);
            a0 *= rs; a1 *= rs; a2 *= rs; a3 *= rs; a4 *= rs; a5 *= rs;
            kAcc += Ei - 207;
        }
    };

    // ---- main scan: t = 1 .. T-1 ----
    for (int t0 = 1; t0 < Tt; t0 += Dp) {
        #pragma unroll
        for (int j = 0; j < Dp; ++j) {
            const int t = t0 + j;
            if (t < Tt) {
                const float g0 = q0[j], g1 = q1[j], gb = qb[j];

                // route sorted values to this lane's label positions
                float x, y, p0v, p1v, p2v;
                x = __shfl_sync(FULLMASK, g0, r0 & 31);
                y = __shfl_sync(FULLMASK, g1, r0 & 31);
                p0v = (r0 < 32) ? x : y;  p0v = (r0 >= Ll) ? gb : p0v;
                x = __shfl_sync(FULLMASK, g0, r1 & 31);
                y = __shfl_sync(FULLMASK, g1, r1 & 31);
                p1v = (r1 < 32) ? x : y;  p1v = (r1 >= Ll) ? gb : p1v;
                x = __shfl_sync(FULLMASK, g0, r2 & 31);
                y = __shfl_sync(FULLMASK, g1, r2 & 31);
                p2v = (r2 < 32) ? x : y;  p2v = (r2 >= Ll) ? gb : p2v;

                const float ebv = gb + EPSV;
                const float E0 = v0 ? ebv : 0.f;
                const float E1 = v1 ? (p0v + EPSV) : 0.f;
                const float E2 = v2 ? ebv : 0.f;
                const float E3 = v3 ? (p1v + EPSV) : 0.f;
                const float E4 = v4 ? ebv : 0.f;
                const float E5 = v5 ? (p2v + EPSV) : 0.f;

                // refill this slot with p[t + Dp]
                int tl = t + Dp; if (tl > Tt - 1) tl = Tt - 1;
                const float* pt = lpb + (size_t)tl * Cc;
                q0[j] = __ldg(pt + cls0);
                q1[j] = __ldg(pt + cls1);
                qb[j] = __ldg(pt + BLANK);

                // cross-lane neighbor: lane l-1's a5
                float n1 = __shfl_up_sync(FULLMASK, a5, 1);
                n1 = (lane == 0) ? 0.f : n1;

                const float t0v = E0 * (a0 + n1);
                const float t1v = E1 * fmaf(M1, n1, a1 + a0);
                const float t2v = E2 * (a2 + a1);
                const float t3v = E3 * fmaf(M3, a1, a3 + a2);
                const float t4v = E4 * (a4 + a3);
                const float t5v = E5 * fmaf(M5, a3, a5 + a4);
                a0 = t0v; a1 = t1v; a2 = t2v; a3 = t3v; a4 = t4v; a5 = t5v;
            }
            if ((j & 3) == 3) renorm();
        }
    }

    // ---- epilogue: loss = -( log(a[2ll] + a[2ll-1]) + kAcc*ln2 ) ----
    const int sl = 2 * ll;
    float vl = pick6(a0, a1, a2, a3, a4, a5, sl % 6);
    vl = __shfl_sync(FULLMASK, vl, sl / 6);
    float vp = 0.f;
    if (ll > 0) {
        const int sp = sl - 1;
        float tv = pick6(a0, a1, a2, a3, a4, a5, sp % 6);
        vp = __shfl_sync(FULLMASK, tv, sp / 6);
    }
    if (lane == 0) {
        out[b] = -(__logf(vl + vp) + (float)kAcc * 0.6931471805599453f);
    }
}

extern "C" void kernel_launch(void* const* d_in, const int* in_sizes, int n_in,
                              void* d_out, int out_size)
{
    const void* u0 = d_in[0];
    const void* u1 = d_in[1];
    const int*   y_true;
    const float* y_pred;
    if (in_sizes[0] < in_sizes[1]) {
        y_true = (const int*)u0;
        y_pred = (const float*)u1;
    } else {
        y_true = (const int*)u1;
        y_pred = (const float*)u0;
    }
    float* out = (float*)d_out;

    const int B = out_size;                 // one loss per row
    ctc_warp_kernel<<<B, 32>>>(y_true, y_pred, out, B);  // 1 warp per CTA
}

// round 15
// speedup vs baseline: 1.1389x; 1.0997x over previous
#include <cuda_runtime.h>
#include <cuda_bf16.h>
#include <cuda_pipeline.h>
#include <cstddef>

// CTC forward loss, probability-domain DP, warp-per-row, barrier-free.
// B=256, T=512, C=1024, L=64, S=129.
// R15 = proven R7 math with the register prefetch ring replaced by a 32-deep
// cp.async shared-memory ring (LDGSTS has no observed outstanding-depth cap,
// vs ~55 for LDG) to push HBM past R7's 80%. One commit group per time step;
// wait_prior(Dp-1) guarantees the slot consumed now was filled Dp steps ago.
// Each lane reads only the smem words its own cp.async wrote -> no syncwarp.
// Scan: 6 states/lane, one shfl_up/step, exact power-of-2 renorm to 2^80
// every 4 steps, single log at the end.

#define FULLMASK 0xffffffffu
#define EPSV 1e-7f

namespace {
constexpr int Tt = 512;
constexpr int Cc = 1024;
constexpr int Ll = 64;
constexpr int BLANK = Cc - 1;
constexpr int Dp = 32;           // cp.async ring depth (steps / commit groups)
}

__device__ __forceinline__ float pick6(float a0, float a1, float a2,
                                       float a3, float a4, float a5, int j) {
    float r = a0;
    r = (j == 1) ? a1 : r;
    r = (j == 2) ? a2 : r;
    r = (j == 3) ? a3 : r;
    r = (j == 4) ? a4 : r;
    r = (j == 5) ? a5 : r;
    return r;
}

__global__ __launch_bounds__(32, 1)
void ctc_warp_kernel(const int* __restrict__ y_true,
                     const float* __restrict__ y_pred,
                     float* __restrict__ out, int B)
{
    const int lane = threadIdx.x & 31;
    const int b = blockIdx.x;
    if (b >= B) return;

    const int*   yt  = y_true + b * Ll;
    const float* lpb = y_pred + (size_t)b * Tt * Cc;

    // ring[slot][arr][lane]: arr 0=blank 1=c0 2=c1 3=c2
    __shared__ float ring[Dp * 4 * 32];

    // ---- label length via ballots (Ll = 64 = 2 x 32) ----
    const int rawA = yt[lane];
    const int rawB = yt[lane + 32];
    const int ll = __popc(__ballot_sync(FULLMASK, rawA != -1)) +
                   __popc(__ballot_sync(FULLMASK, rawB != -1));
    const int Svalid = 2 * ll + 1;

    auto labAt = [&](int idx) -> int {
        if (idx < 0 || idx >= Ll) return BLANK;
        const int v = yt[idx];
        return (v < 0) ? BLANK : v;
    };
    const int base3 = 3 * lane;
    const int cm1 = labAt(base3 - 1);
    const int c0  = labAt(base3);        // class of state 6l+1
    const int c1  = labAt(base3 + 1);    // class of state 6l+3
    const int c2  = labAt(base3 + 2);    // class of state 6l+5

    const int s0 = 6 * lane;
    const bool v0 = (s0 + 0) < Svalid;
    const bool v1 = (s0 + 1) < Svalid;
    const bool v2 = (s0 + 2) < Svalid;
    const bool v3 = (s0 + 3) < Svalid;
    const bool v4 = (s0 + 4) < Svalid;
    const bool v5 = (s0 + 5) < Svalid;
    const float M1 = ((s0 + 1) >= 2 && c0 != BLANK && c0 != cm1) ? 1.f : 0.f;
    const float M3 = ((s0 + 3) >= 2 && c1 != BLANK && c1 != c0)  ? 1.f : 0.f;
    const float M5 = ((s0 + 5) >= 2 && c2 != BLANK && c2 != c1)  ? 1.f : 0.f;

    // ---- alpha registers, t = 0 init (biased by 2^40) ----
    const float BIAS = __uint_as_float((unsigned)(40 + 127) << 23);  // 2^40
    float a0 = 0.f, a1 = 0.f, a2 = 0.f, a3 = 0.f, a4 = 0.f, a5 = 0.f;
    if (lane == 0) {
        a0 = (__ldg(lpb + BLANK) + EPSV) * BIAS;
        if (ll > 0) a1 = (__ldg(lpb + c0) + EPSV) * BIAS;
    }
    int kAcc = -40;

    // ---- prefill ring: slot i <- emissions at time 1+i; one group/slot ----
    #pragma unroll
    for (int i = 0; i < Dp; ++i) {
        const float* pt = lpb + (size_t)(1 + i) * Cc;   // 1+i <= 32 < Tt
        float* base = &ring[(i * 4) * 32 + lane];
        __pipeline_memcpy_async(base + 0 * 32, pt + BLANK, 4);
        __pipeline_memcpy_async(base + 1 * 32, pt + c0,    4);
        __pipeline_memcpy_async(base + 2 * 32, pt + c1,    4);
        __pipeline_memcpy_async(base + 3 * 32, pt + c2,    4);
        __pipeline_commit();
    }

    // exact power-of-2 renorm: bring warp-max exponent to +80
    auto renorm = [&]() {
        float m = fmaxf(fmaxf(fmaxf(a0, a1), fmaxf(a2, a3)), fmaxf(a4, a5));
        const unsigned mi = __reduce_max_sync(FULLMASK, __float_as_uint(m));
        const unsigned ebits = mi & 0x7f800000u;
        if (ebits != 0u) {
            const int Ei = (int)(ebits >> 23);
            const float rs = __uint_as_float((unsigned)(334 - Ei) << 23);
            a0 *= rs; a1 *= rs; a2 *= rs; a3 *= rs; a4 *= rs; a5 *= rs;
            kAcc += Ei - 207;
        }
    };

    // ---- main scan: t = 1 .. T-1 ----
    for (int t0 = 1; t0 < Tt; t0 += 16) {
        #pragma unroll
        for (int j = 0; j < 16; ++j) {
            const int t = t0 + j;
            if (t < Tt) {
                const int slot = (t - 1) & (Dp - 1);

                // oldest outstanding group (this slot's fill) must be done
                __pipeline_wait_prior(Dp - 1);
                float* base = &ring[(slot * 4) * 32 + lane];
                const float gb = base[0 * 32];
                const float g0 = base[1 * 32];
                const float g1 = base[2 * 32];
                const float g2 = base[3 * 32];

                // refill this slot with time t + Dp (clamped), new group
                int tl = t + Dp; if (tl > Tt - 1) tl = Tt - 1;
                const float* pt = lpb + (size_t)tl * Cc;
                __pipeline_memcpy_async(base + 0 * 32, pt + BLANK, 4);
                __pipeline_memcpy_async(base + 1 * 32, pt + c0,    4);
                __pipeline_memcpy_async(base + 2 * 32, pt + c1,    4);
                __pipeline_memcpy_async(base + 3 * 32, pt + c2,    4);
                __pipeline_commit();

                const float ebv = gb + EPSV;
                const float E0 = v0 ? ebv : 0.f;
                const float E1 = v1 ? (g0 + EPSV) : 0.f;
                const float E2 = v2 ? ebv : 0.f;
                const float E3 = v3 ? (g1 + EPSV) : 0.f;
                const float E4 = v4 ? ebv : 0.f;
                const float E5 = v5 ? (g2 + EPSV) : 0.f;

                float n1 = __shfl_up_sync(FULLMASK, a5, 1);
                n1 = (lane == 0) ? 0.f : n1;

                const float t0v = E0 * (a0 + n1);
                const float t1v = E1 * fmaf(M1, n1, a1 + a0);
                const float t2v = E2 * (a2 + a1);
                const float t3v = E3 * fmaf(M3, a1, a3 + a2);
                const float t4v = E4 * (a4 + a3);
                const float t5v = E5 * fmaf(M5, a3, a5 + a4);
                a0 = t0v; a1 = t1v; a2 = t2v; a3 = t3v; a4 = t4v; a5 = t5v;
            }
            if ((j & 3) == 3) renorm();    // 4-step renorm cadence
        }
    }

    // ---- epilogue: loss = -( log(a[2ll] + a[2ll-1]) + kAcc*ln2 ) ----
    const int sl = 2 * ll;
    float vl = pick6(a0, a1, a2, a3, a4, a5, sl % 6);
    vl = __shfl_sync(FULLMASK, vl, sl / 6);
    float vp = 0.f;
    if (ll > 0) {
        const int sp = sl - 1;
        float tv = pick6(a0, a1, a2, a3, a4, a5, sp % 6);
        vp = __shfl_sync(FULLMASK, tv, sp / 6);
    }
    if (lane == 0) {
        out[b] = -(__logf(vl + vp) + (float)kAcc * 0.6931471805599453f);
    }
}

extern "C" void kernel_launch(void* const* d_in, const int* in_sizes, int n_in,
                              void* d_out, int out_size)
{
    const void* u0 = d_in[0];
    const void* u1 = d_in[1];
    const int*   y_true;
    const float* y_pred;
    if (in_sizes[0] < in_sizes[1]) {
        y_true = (const int*)u0;
        y_pred = (const float*)u1;
    } else {
        y_true = (const int*)u1;
        y_pred = (const float*)u0;
    }
    float* out = (float*)d_out;

    const int B = out_size;                 // one loss per row
    ctc_warp_kernel<<<B, 32>>>(y_true, y_pred, out, B);  // 1 warp per CTA
}

// round 16
// speedup vs baseline: 1.1584x; 1.0170x over previous
#include <cuda_runtime.h>
#include <cuda_bf16.h>
#include <cstddef>

// CTC forward loss, probability-domain DP, warp-per-row, barrier-free.
// B=256, T=512, C=1024, L=64, S=129.
// R16 = proven R7 kernel with prefetch ring deepened 16 -> 24 steps to raise
// chip-wide in-flight bytes (the remaining candidate binder at 80% dram).
// Lane l holds states 6l..6l+5 in registers; one shfl_up per step; exact
// power-of-2 renorm to target max 2^80 every 4 steps; single log at the end.

#define FULLMASK 0xffffffffu
#define EPSV 1e-7f

namespace {
constexpr int Tt = 512;
constexpr int Cc = 1024;
constexpr int Ll = 64;
constexpr int BLANK = Cc - 1;
constexpr int Dp = 24;           // prefetch ring depth (steps), divisible by 4
}

__device__ __forceinline__ float pick6(float a0, float a1, float a2,
                                       float a3, float a4, float a5, int j) {
    float r = a0;
    r = (j == 1) ? a1 : r;
    r = (j == 2) ? a2 : r;
    r = (j == 3) ? a3 : r;
    r = (j == 4) ? a4 : r;
    r = (j == 5) ? a5 : r;
    return r;
}

__global__ __launch_bounds__(32, 1)
void ctc_warp_kernel(const int* __restrict__ y_true,
                     const float* __restrict__ y_pred,
                     float* __restrict__ out, int B)
{
    const int lane = threadIdx.x & 31;
    const int b = blockIdx.x;
    if (b >= B) return;

    const int*   yt  = y_true + b * Ll;
    const float* lpb = y_pred + (size_t)b * Tt * Cc;

    // ---- label length via ballots (Ll = 64 = 2 x 32) ----
    const int rawA = yt[lane];
    const int rawB = yt[lane + 32];
    const int ll = __popc(__ballot_sync(FULLMASK, rawA != -1)) +
                   __popc(__ballot_sync(FULLMASK, rawB != -1));
    const int Svalid = 2 * ll + 1;

    auto labAt = [&](int idx) -> int {
        if (idx < 0 || idx >= Ll) return BLANK;
        const int v = yt[idx];
        return (v < 0) ? BLANK : v;
    };
    const int base3 = 3 * lane;
    const int cm1 = labAt(base3 - 1);
    const int c0  = labAt(base3);        // class of state 6l+1
    const int c1  = labAt(base3 + 1);    // class of state 6l+3
    const int c2  = labAt(base3 + 2);    // class of state 6l+5

    const int s0 = 6 * lane;
    const bool v0 = (s0 + 0) < Svalid;
    const bool v1 = (s0 + 1) < Svalid;
    const bool v2 = (s0 + 2) < Svalid;
    const bool v3 = (s0 + 3) < Svalid;
    const bool v4 = (s0 + 4) < Svalid;
    const bool v5 = (s0 + 5) < Svalid;
    // allow2 only on odd (label) states: ext[s]!=blank && ext[s]!=ext[s-2]
    const float M1 = ((s0 + 1) >= 2 && c0 != BLANK && c0 != cm1) ? 1.f : 0.f;
    const float M3 = ((s0 + 3) >= 2 && c1 != BLANK && c1 != c0)  ? 1.f : 0.f;
    const float M5 = ((s0 + 5) >= 2 && c2 != BLANK && c2 != c1)  ? 1.f : 0.f;

    // ---- alpha registers, t = 0 init (biased by 2^40) ----
    const float BIAS = __uint_as_float((unsigned)(40 + 127) << 23);  // 2^40
    float a0 = 0.f, a1 = 0.f, a2 = 0.f, a3 = 0.f, a4 = 0.f, a5 = 0.f;
    if (lane == 0) {
        a0 = (__ldg(lpb + BLANK) + EPSV) * BIAS;
        if (ll > 0) a1 = (__ldg(lpb + c0) + EPSV) * BIAS;
    }
    int kAcc = -40;  // accumulated power-of-2 exponent removed by renorms

    // ---- prefetch ring: slot i holds p[t] for step t = t0 + i ----
    float pb[Dp], p0[Dp], p1[Dp], p2[Dp];
    #pragma unroll
    for (int i = 0; i < Dp; ++i) {
        const float* pt = lpb + (size_t)(1 + i) * Cc;   // 1+i <= 24 < Tt
        pb[i] = __ldg(pt + BLANK);
        p0[i] = __ldg(pt + c0);
        p1[i] = __ldg(pt + c1);
        p2[i] = __ldg(pt + c2);
    }

    // exact power-of-2 renorm: bring warp-max exponent to +80
    auto renorm = [&]() {
        float m = fmaxf(fmaxf(fmaxf(a0, a1), fmaxf(a2, a3)), fmaxf(a4, a5));
        const unsigned mi = __reduce_max_sync(FULLMASK, __float_as_uint(m));
        const unsigned ebits = mi & 0x7f800000u;
        if (ebits != 0u) {                                   // uniform branch
            const int Ei = (int)(ebits >> 23);               // biased exponent
            // scale = 2^(80 - (Ei-127)) = 2^(207-Ei); field = 334-Ei
            const float rs = __uint_as_float((unsigned)(334 - Ei) << 23);
            a0 *= rs; a1 *= rs; a2 *= rs; a3 *= rs; a4 *= rs; a5 *= rs;
            kAcc += Ei - 207;
        }
    };

    // ---- main scan: t = 1 .. T-1, unrolled by Dp, renorm every 4 steps ----
    for (int t0 = 1; t0 < Tt; t0 += Dp) {
        #pragma unroll
        for (int j = 0; j < Dp; ++j) {
            const int t = t0 + j;
            if (t < Tt) {
                // emissions for step t (slot j), validity folded in
                const float ebv = pb[j] + EPSV;
                const float E0 = v0 ? ebv : 0.f;
                const float E1 = v1 ? (p0[j] + EPSV) : 0.f;
                const float E2 = v2 ? ebv : 0.f;
                const float E3 = v3 ? (p1[j] + EPSV) : 0.f;
                const float E4 = v4 ? ebv : 0.f;
                const float E5 = v5 ? (p2[j] + EPSV) : 0.f;

                // refill this slot with p[t + Dp]
                int tl = t + Dp; if (tl > Tt - 1) tl = Tt - 1;
                const float* pt = lpb + (size_t)tl * Cc;
                pb[j] = __ldg(pt + BLANK);
                p0[j] = __ldg(pt + c0);
                p1[j] = __ldg(pt + c1);
                p2[j] = __ldg(pt + c2);

                // cross-lane neighbor: lane l-1's a5 (= s0-1; also skip src of s0+1)
                float n1 = __shfl_up_sync(FULLMASK, a5, 1);
                n1 = (lane == 0) ? 0.f : n1;

                const float t0v = E0 * (a0 + n1);                 // blank: no skip
                const float t1v = E1 * fmaf(M1, n1, a1 + a0);
                const float t2v = E2 * (a2 + a1);
                const float t3v = E3 * fmaf(M3, a1, a3 + a2);
                const float t4v = E4 * (a4 + a3);
                const float t5v = E5 * fmaf(M5, a3, a5 + a4);
                a0 = t0v; a1 = t1v; a2 = t2v; a3 = t3v; a4 = t4v; a5 = t5v;
            }
            if ((j & 3) == 3) renorm();    // 4-step renorm cadence
        }
    }

    // ---- epilogue: loss = -( log(a[2ll] + a[2ll-1]) + kAcc*ln2 ) ----
    const int sl = 2 * ll;
    float vl = pick6(a0, a1, a2, a3, a4, a5, sl % 6);
    vl = __shfl_sync(FULLMASK, vl, sl / 6);
    float vp = 0.f;
    if (ll > 0) {                                            // uniform
        const int sp = sl - 1;
        float tv = pick6(a0, a1, a2, a3, a4, a5, sp % 6);
        vp = __shfl_sync(FULLMASK, tv, sp / 6);
    }
    if (lane == 0) {
        out[b] = -(__logf(vl + vp) + (float)kAcc * 0.6931471805599453f);
    }
}

extern "C" void kernel_launch(void* const* d_in, const int* in_sizes, int n_in,
                              void* d_out, int out_size)
{
    const void* u0 = d_in[0];
    const void* u1 = d_in[1];
    const int*   y_true;
    const float* y_pred;
    if (in_sizes[0] < in_sizes[1]) {
        y_true = (const int*)u0;
        y_pred = (const float*)u1;
    } else {
        y_true = (const int*)u1;
        y_pred = (const float*)u0;
    }
    float* out = (float*)d_out;

    const int B = out_size;                 // one loss per row
    ctc_warp_kernel<<<B, 32>>>(y_true, y_pred, out, B);  // 1 warp per CTA
}